// round 1
// baseline (speedup 1.0000x reference)
#include <cuda_runtime.h>

#define NB 32
#define NA 8400
#define NC 80
#define NM 64
#define KTOP 13
#define FEPS 1e-9f

// Persistent scratch (device globals; no allocation allowed)
__device__ int                 g_topk[NB * NM * KTOP];   // top-13 anchor idx per (b,m)
__device__ unsigned long long  g_mask[NB * NA];          // final mask_positive bits per anchor
__device__ float               g_maxmet[NB * NM];        // max over a of align*mask
__device__ float               g_maxiou[NB * NM];        // max over a of iou*mask

__device__ __forceinline__ float iou_fn(float gx1, float gy1, float gx2, float gy2,
                                        float garea, float4 p) {
    float ix1 = fmaxf(gx1, p.x), iy1 = fmaxf(gy1, p.y);
    float ix2 = fminf(gx2, p.z), iy2 = fminf(gy2, p.w);
    float ov  = fmaxf(ix2 - ix1, 0.f) * fmaxf(iy2 - iy1, 0.f);
    float pa  = fmaxf(p.z - p.x, 0.f) * fmaxf(p.w - p.y, 0.f);
    return ov / (garea + pa - ov + FEPS);
}

// ---------------------------------------------------------------------------
// Kernel 0: zero the per-(b,m) max accumulators
// ---------------------------------------------------------------------------
__global__ void k_init() {
    int i = blockIdx.x * blockDim.x + threadIdx.x;
    if (i < NB * NM) { g_maxmet[i] = 0.f; g_maxiou[i] = 0.f; }
}

// ---------------------------------------------------------------------------
// Kernel 1: per (b,m) row — compute metrics, select top-13 (lowest-index ties)
// ---------------------------------------------------------------------------
__global__ __launch_bounds__(256)
void k_topk(const float* __restrict__ ps,   // pred_scores  [B,A,C]
            const float* __restrict__ pb,   // pred_bboxes  [B,A,4]
            const float* __restrict__ ap,   // anchor_points[A,2]
            const int*   __restrict__ gl,   // gt_labels    [B,M]
            const float* __restrict__ gb,   // gt_bboxes    [B,M,4]
            const float* __restrict__ pm)   // pad_gt_mask  [B,M]
{
    int bm = blockIdx.x;
    if (pm[bm] == 0.f) return;              // padded gt: row never used downstream
    int b = bm / NM;

    __shared__ float sm[NA];
    __shared__ float rv[256];
    __shared__ int   ri[256];

    float gx1 = gb[bm * 4 + 0], gy1 = gb[bm * 4 + 1];
    float gx2 = gb[bm * 4 + 2], gy2 = gb[bm * 4 + 3];
    float garea = fmaxf(gx2 - gx1, 0.f) * fmaxf(gy2 - gy1, 0.f);
    int   lab   = gl[bm];
    int   t     = threadIdx.x;

    const float4* pbv = (const float4*)pb;
    const float2* apv = (const float2*)ap;

    for (int a = t; a < NA; a += 256) {
        float2 c = apv[a];
        float d = fminf(fminf(c.x - gx1, c.y - gy1), fminf(gx2 - c.x, gy2 - c.y));
        float met = 0.f;
        if (d > FEPS) {
            float4 p   = pbv[b * NA + a];
            float  iou = iou_fn(gx1, gy1, gx2, gy2, garea, p);
            float  cls = __ldg(&ps[((size_t)(b * NA + a)) * NC + lab]);
            float  i2  = iou * iou;
            met = cls * (i2 * i2 * i2);
        }
        sm[a] = met;
    }
    __syncthreads();

    // 13 iterative argmax passes; strict '>' keeps the lowest index on ties,
    // matching jax.lax.top_k tie-breaking exactly.
    for (int k = 0; k < KTOP; k++) {
        float bv = -1.f; int bi = 0;
        for (int a = t; a < NA; a += 256) {
            float v = sm[a];
            if (v > bv) { bv = v; bi = a; }
        }
        rv[t] = bv; ri[t] = bi;
        __syncthreads();
        for (int s = 128; s > 0; s >>= 1) {
            if (t < s) {
                float v2 = rv[t + s]; int i2 = ri[t + s];
                if (v2 > rv[t] || (v2 == rv[t] && i2 < ri[t])) { rv[t] = v2; ri[t] = i2; }
            }
            __syncthreads();
        }
        if (t == 0) {
            g_topk[bm * KTOP + k] = ri[0];
            sm[ri[0]] = -2.f;       // remove from further consideration
        }
        __syncthreads();
    }
}

// ---------------------------------------------------------------------------
// Kernel 2: per anchor — build mask, resolve multi-assignment, emit labels +
//           bboxes, accumulate per-(b,m) maxima via atomicMax on float bits.
// ---------------------------------------------------------------------------
__global__ __launch_bounds__(256)
void k_assign(const float* __restrict__ ps,
              const float* __restrict__ pb,
              const float* __restrict__ ap,
              const int*   __restrict__ gl,
              const float* __restrict__ gb,
              const float* __restrict__ pm,
              const int*   __restrict__ bgp,
              float* __restrict__ out_lab,   // [B,A]  (labels as float)
              float* __restrict__ out_box)   // [B,A,4]
{
    int b = blockIdx.y;
    int a = blockIdx.x * 256 + threadIdx.x;
    int t = threadIdx.x;

    __shared__ int   stk[NM * KTOP];
    __shared__ float sgb[NM * 4];
    __shared__ int   sgl[NM];
    __shared__ float spm[NM];

    for (int i = t; i < NM * KTOP; i += 256) stk[i] = g_topk[b * NM * KTOP + i];
    for (int i = t; i < NM * 4;   i += 256) sgb[i] = gb[b * NM * 4 + i];
    if (t < NM) { sgl[t] = gl[b * NM + t]; spm[t] = pm[b * NM + t]; }
    __syncthreads();
    if (a >= NA) return;

    float2 c = ((const float2*)ap)[a];
    float4 p = ((const float4*)pb)[b * NA + a];

    unsigned long long bits = 0ull;
    int cnt = 0;
    for (int m = 0; m < NM; m++) {
        if (spm[m] == 0.f) continue;
        float gx1 = sgb[4*m], gy1 = sgb[4*m+1], gx2 = sgb[4*m+2], gy2 = sgb[4*m+3];
        float d = fminf(fminf(c.x - gx1, c.y - gy1), fminf(gx2 - c.x, gy2 - c.y));
        if (!(d > FEPS)) continue;
        bool intop = false;
        #pragma unroll
        for (int k = 0; k < KTOP; k++) intop |= (stk[m * KTOP + k] == a);
        if (intop) { bits |= (1ull << m); cnt++; }
    }

    if (cnt > 1) {
        // multi-assigned anchor: replace column with argmax-IoU over ALL m
        float bestv = -1.f; int bestm = 0;
        for (int m = 0; m < NM; m++) {
            float gx1 = sgb[4*m], gy1 = sgb[4*m+1], gx2 = sgb[4*m+2], gy2 = sgb[4*m+3];
            float garea = fmaxf(gx2 - gx1, 0.f) * fmaxf(gy2 - gy1, 0.f);
            float iou = iou_fn(gx1, gy1, gx2, gy2, garea, p);
            if (iou > bestv) { bestv = iou; bestm = m; }
        }
        bits = 1ull << bestm;
    }
    g_mask[b * NA + a] = bits;

    int first = bits ? (__ffsll((long long)bits) - 1) : 0;
    int bg = *bgp;
    out_lab[b * NA + a] = (float)(bits ? sgl[first] : bg);
    float4 ob;
    ob.x = sgb[4*first]; ob.y = sgb[4*first+1]; ob.z = sgb[4*first+2]; ob.w = sgb[4*first+3];
    ((float4*)out_box)[b * NA + a] = ob;

    // accumulate max(align*mask) and max(iou*mask) per (b,m)
    unsigned long long mm = bits;
    while (mm) {
        int m = __ffsll((long long)mm) - 1;
        mm &= mm - 1;
        float gx1 = sgb[4*m], gy1 = sgb[4*m+1], gx2 = sgb[4*m+2], gy2 = sgb[4*m+3];
        float garea = fmaxf(gx2 - gx1, 0.f) * fmaxf(gy2 - gy1, 0.f);
        float iou = iou_fn(gx1, gy1, gx2, gy2, garea, p);
        float cls = __ldg(&ps[((size_t)(b * NA + a)) * NC + sgl[m]]);
        float i2 = iou * iou;
        float align = cls * (i2 * i2 * i2);
        atomicMax((int*)&g_maxmet[b * NM + m], __float_as_int(align));
        atomicMax((int*)&g_maxiou[b * NM + m], __float_as_int(iou));
    }
}

// ---------------------------------------------------------------------------
// Kernel 3: per anchor — compute normalized score factor, scatter into the
//           (pre-zeroed) assigned_scores tensor. Only ~26K anchors do work.
// ---------------------------------------------------------------------------
__global__ __launch_bounds__(256)
void k_scores(const float* __restrict__ ps,
              const float* __restrict__ pb,
              const int*   __restrict__ gl,
              const float* __restrict__ gb,
              const int*   __restrict__ bgp,
              float* __restrict__ out_sc)    // [B,A,C]
{
    int idx = blockIdx.x * 256 + threadIdx.x;
    if (idx >= NB * NA) return;
    unsigned long long bits = g_mask[idx];
    if (!bits) return;                       // scores row stays zero (memset)
    int b = idx / NA;

    float4 p = ((const float4*)pb)[idx];
    float factor = 0.f;
    int first = __ffsll((long long)bits) - 1;

    unsigned long long mm = bits;
    while (mm) {
        int m = __ffsll((long long)mm) - 1;
        mm &= mm - 1;
        int bm = b * NM + m;
        float gx1 = gb[bm*4], gy1 = gb[bm*4+1], gx2 = gb[bm*4+2], gy2 = gb[bm*4+3];
        float garea = fmaxf(gx2 - gx1, 0.f) * fmaxf(gy2 - gy1, 0.f);
        float iou = iou_fn(gx1, gy1, gx2, gy2, garea, p);
        float cls = __ldg(&ps[(size_t)idx * NC + gl[bm]]);
        float i2 = iou * iou;
        float align = cls * (i2 * i2 * i2);
        float v = align / (g_maxmet[bm] + FEPS) * g_maxiou[bm];
        factor = fmaxf(factor, v);
    }

    int lab = gl[b * NM + first];            // always a real class (< C) here
    int bg  = *bgp;
    int col = (lab < bg) ? lab : (lab - 1);  // one_hot(C+1)[..., keep != bg]
    out_sc[(size_t)idx * NC + col] = factor;
}

// ---------------------------------------------------------------------------
extern "C" void kernel_launch(void* const* d_in, const int* in_sizes, int n_in,
                              void* d_out, int out_size) {
    const float* ps  = (const float*)d_in[0];  // pred_scores   [B,A,C]
    const float* pb  = (const float*)d_in[1];  // pred_bboxes   [B,A,4]
    const float* ap  = (const float*)d_in[2];  // anchor_points [A,2]
    const int*   gl  = (const int*)  d_in[3];  // gt_labels     [B,M,1]
    const float* gb  = (const float*)d_in[4];  // gt_bboxes     [B,M,4]
    const float* pm  = (const float*)d_in[5];  // pad_gt_mask   [B,M,1]
    const int*   bgp = (const int*)  d_in[6];  // bg_index scalar

    float* out      = (float*)d_out;
    float* out_lab  = out;                              // [B,A]
    float* out_box  = out + (size_t)NB * NA;            // [B,A,4]
    float* out_sc   = out + (size_t)NB * NA * 5;        // [B,A,C]

    // zero the scores region (memset node is graph-capturable)
    cudaMemsetAsync(out_sc, 0, (size_t)NB * NA * NC * sizeof(float));

    k_init<<<(NB * NM + 255) / 256, 256>>>();
    k_topk<<<NB * NM, 256>>>(ps, pb, ap, gl, gb, pm);
    dim3 ga((NA + 255) / 256, NB);
    k_assign<<<ga, 256>>>(ps, pb, ap, gl, gb, pm, bgp, out_lab, out_box);
    k_scores<<<(NB * NA + 255) / 256, 256>>>(ps, pb, gl, gb, bgp, out_sc);
}

// round 2
// speedup vs baseline: 1.7052x; 1.7052x over previous
#include <cuda_runtime.h>

#define NB 32
#define NA 8400
#define NC 80
#define NM 64
#define KTOP 13
#define FEPS 1e-9f
#define CAP 2048

// Persistent scratch (device globals; no allocation allowed)
__device__ unsigned long long g_bits[NB * NA];   // pre-resolution topk∩ingts bits
__device__ unsigned long long g_mask[NB * NA];   // final mask_positive bits
__device__ float              g_maxmet[NB * NM];
__device__ float              g_maxiou[NB * NM];

__device__ __forceinline__ float iou_fn(float gx1, float gy1, float gx2, float gy2,
                                        float garea, float4 p) {
    float ix1 = fmaxf(gx1, p.x), iy1 = fmaxf(gy1, p.y);
    float ix2 = fminf(gx2, p.z), iy2 = fminf(gy2, p.w);
    float ov  = fmaxf(ix2 - ix1, 0.f) * fmaxf(iy2 - iy1, 0.f);
    float pa  = fmaxf(p.z - p.x, 0.f) * fmaxf(p.w - p.y, 0.f);
    return ov / (garea + pa - ov + FEPS);
}

// ---------------------------------------------------------------------------
__global__ void k_init() {
    int i = blockIdx.x * blockDim.x + threadIdx.x;
    if (i < NB * NA) g_bits[i] = 0ull;
    if (i < NB * NM) { g_maxmet[i] = 0.f; g_maxiou[i] = 0.f; }
}

// ---------------------------------------------------------------------------
// Kernel 1: per (b,m) row — compact inside-anchor candidates, pick top-13 by
// unique packed key (value desc, anchor index asc), scatter bits per anchor.
// ---------------------------------------------------------------------------
__global__ __launch_bounds__(256)
void k_topk(const float* __restrict__ ps,   // pred_scores  [B,A,C]
            const float* __restrict__ pb,   // pred_bboxes  [B,A,4]
            const float* __restrict__ ap,   // anchor_points[A,2]
            const int*   __restrict__ gl,   // gt_labels    [B,M]
            const float* __restrict__ gb,   // gt_bboxes    [B,M,4]
            const float* __restrict__ pm)   // pad_gt_mask  [B,M]
{
    int bm = blockIdx.x;
    if (pm[bm] == 0.f) return;              // padded row: contributes nothing
    int b = bm >> 6, m = bm & 63;

    __shared__ unsigned long long keys[CAP];
    __shared__ unsigned long long wred[8];
    __shared__ unsigned long long s_kprev;
    __shared__ int s_cnt;

    int t = threadIdx.x, lane = t & 31;
    if (t == 0) s_cnt = 0;
    __syncthreads();

    float gx1 = gb[bm * 4 + 0], gy1 = gb[bm * 4 + 1];
    float gx2 = gb[bm * 4 + 2], gy2 = gb[bm * 4 + 3];
    float garea = fmaxf(gx2 - gx1, 0.f) * fmaxf(gy2 - gy1, 0.f);
    int lab = gl[bm];

    const float4* pbv = (const float4*)pb + (size_t)b * NA;
    const float2* apv = (const float2*)ap;
    const float*  psb = ps + (size_t)b * NA * NC + lab;

    // Phase 1: compaction (warp-aggregated shared atomics)
    for (int base = 0; base < NA; base += 256) {
        int a = base + t;
        bool inb = a < NA;
        float d = -1.f;
        if (inb) {
            float2 c = apv[a];
            d = fminf(fminf(c.x - gx1, c.y - gy1), fminf(gx2 - c.x, gy2 - c.y));
        }
        bool pred = inb && (d > FEPS);
        unsigned act = __ballot_sync(0xffffffffu, pred);
        if (pred) {
            float4 p   = pbv[a];
            float  iou = iou_fn(gx1, gy1, gx2, gy2, garea, p);
            float  cls = __ldg(psb + (size_t)a * NC);
            float  i2  = iou * iou;
            float  met = cls * (i2 * i2 * i2);
            // unique key: (value desc, anchor idx asc) == jax.lax.top_k order
            unsigned long long key =
                ((unsigned long long)__float_as_uint(met) << 32) | (unsigned)(NA - a);
            int rank   = __popc(act & ((1u << lane) - 1u));
            int leader = __ffs(act) - 1;
            int pos;
            if (lane == leader) pos = atomicAdd(&s_cnt, __popc(act));
            pos = __shfl_sync(act, pos, leader) + rank;
            if (pos < CAP) keys[pos] = key;
        }
    }
    __syncthreads();
    int n = min(s_cnt, CAP);

    // Phase 2: 13 passes of "max key strictly below previous winner"
    unsigned long long kprev = 0xFFFFFFFFFFFFFFFFull;
    for (int k = 0; k < KTOP; k++) {
        unsigned long long best = 0ull;
        for (int i = t; i < n; i += 256) {
            unsigned long long kk = keys[i];
            if (kk < kprev && kk > best) best = kk;
        }
        #pragma unroll
        for (int s = 16; s; s >>= 1) {
            unsigned long long o = __shfl_down_sync(0xffffffffu, best, s);
            if (o > best) best = o;
        }
        if (lane == 0) wred[t >> 5] = best;
        __syncthreads();
        if (t < 32) {
            unsigned long long b2 = (t < 8) ? wred[t] : 0ull;
            #pragma unroll
            for (int s = 4; s; s >>= 1) {
                unsigned long long o = __shfl_down_sync(0xffffffffu, b2, s);
                if (o > b2) b2 = o;
            }
            if (t == 0) {
                s_kprev = b2;
                if (b2) {
                    int aidx = NA - (int)(b2 & 0xffffffffu);
                    atomicOr(&g_bits[(size_t)b * NA + aidx], 1ull << m);
                }
            }
        }
        __syncthreads();
        kprev = s_kprev;
        if (!kprev) break;                  // uniform: fewer than 13 candidates
    }
}

// ---------------------------------------------------------------------------
// Kernel 2: per anchor — resolve multi-assignment, emit labels/bboxes, maxima
// ---------------------------------------------------------------------------
__global__ __launch_bounds__(256)
void k_assign(const float* __restrict__ ps,
              const float* __restrict__ pb,
              const int*   __restrict__ gl,
              const float* __restrict__ gb,
              const int*   __restrict__ bgp,
              float* __restrict__ out_lab,   // [B,A]
              float* __restrict__ out_box)   // [B,A,4]
{
    int b = blockIdx.y;
    int t = threadIdx.x;
    __shared__ float sgb[NM * 4];
    __shared__ int   sgl[NM];
    if (t < NM * 4) sgb[t] = gb[b * NM * 4 + t];
    if (t < NM)     sgl[t] = gl[b * NM + t];
    __syncthreads();

    int a = blockIdx.x * 256 + t;
    if (a >= NA) return;
    size_t ia = (size_t)b * NA + a;
    unsigned long long bits = g_bits[ia];

    if (!bits) {                            // fast path: background anchor
        g_mask[ia] = 0ull;
        out_lab[ia] = (float)(*bgp);
        float4 ob = {sgb[0], sgb[1], sgb[2], sgb[3]};  // argmax(0)=0 row
        ((float4*)out_box)[ia] = ob;
        return;
    }

    float4 p = ((const float4*)pb)[ia];
    if (__popcll(bits) > 1) {
        // multi-assigned: argmax IoU over ALL m (incl. padded, per reference)
        float bestv = -1.f; int bestm = 0;
        for (int m = 0; m < NM; m++) {
            float gx1 = sgb[4*m], gy1 = sgb[4*m+1], gx2 = sgb[4*m+2], gy2 = sgb[4*m+3];
            float ga = fmaxf(gx2 - gx1, 0.f) * fmaxf(gy2 - gy1, 0.f);
            float iou = iou_fn(gx1, gy1, gx2, gy2, ga, p);
            if (iou > bestv) { bestv = iou; bestm = m; }
        }
        bits = 1ull << bestm;
    }
    g_mask[ia] = bits;

    int first = __ffsll((long long)bits) - 1;
    out_lab[ia] = (float)sgl[first];
    float4 ob = {sgb[4*first], sgb[4*first+1], sgb[4*first+2], sgb[4*first+3]};
    ((float4*)out_box)[ia] = ob;

    unsigned long long mm = bits;
    while (mm) {
        int m = __ffsll((long long)mm) - 1;
        mm &= mm - 1;
        float gx1 = sgb[4*m], gy1 = sgb[4*m+1], gx2 = sgb[4*m+2], gy2 = sgb[4*m+3];
        float ga = fmaxf(gx2 - gx1, 0.f) * fmaxf(gy2 - gy1, 0.f);
        float iou = iou_fn(gx1, gy1, gx2, gy2, ga, p);
        float cls = __ldg(&ps[ia * NC + sgl[m]]);
        float i2 = iou * iou;
        float align = cls * (i2 * i2 * i2);
        atomicMax((int*)&g_maxmet[b * NM + m], __float_as_int(align));
        atomicMax((int*)&g_maxiou[b * NM + m], __float_as_int(iou));
    }
}

// ---------------------------------------------------------------------------
// Kernel 3: per positive anchor — normalized score scatter into zeroed region
// ---------------------------------------------------------------------------
__global__ __launch_bounds__(256)
void k_scores(const float* __restrict__ ps,
              const float* __restrict__ pb,
              const int*   __restrict__ gl,
              const float* __restrict__ gb,
              const int*   __restrict__ bgp,
              float* __restrict__ out_sc)    // [B,A,C]
{
    int idx = blockIdx.x * 256 + threadIdx.x;
    if (idx >= NB * NA) return;
    unsigned long long bits = g_mask[idx];
    if (!bits) return;
    int b = idx / NA;

    float4 p = ((const float4*)pb)[idx];
    float factor = 0.f;
    int first = __ffsll((long long)bits) - 1;

    unsigned long long mm = bits;
    while (mm) {
        int m = __ffsll((long long)mm) - 1;
        mm &= mm - 1;
        int bmi = b * NM + m;
        float gx1 = gb[bmi*4], gy1 = gb[bmi*4+1], gx2 = gb[bmi*4+2], gy2 = gb[bmi*4+3];
        float ga = fmaxf(gx2 - gx1, 0.f) * fmaxf(gy2 - gy1, 0.f);
        float iou = iou_fn(gx1, gy1, gx2, gy2, ga, p);
        float cls = __ldg(&ps[(size_t)idx * NC + gl[bmi]]);
        float i2 = iou * iou;
        float align = cls * (i2 * i2 * i2);
        float v = align / (g_maxmet[bmi] + FEPS) * g_maxiou[bmi];
        factor = fmaxf(factor, v);
    }

    int lab = gl[b * NM + first];
    int bg  = *bgp;
    int col = (lab < bg) ? lab : (lab - 1);
    out_sc[(size_t)idx * NC + col] = factor;
}

// ---------------------------------------------------------------------------
extern "C" void kernel_launch(void* const* d_in, const int* in_sizes, int n_in,
                              void* d_out, int out_size) {
    const float* ps  = (const float*)d_in[0];
    const float* pb  = (const float*)d_in[1];
    const float* ap  = (const float*)d_in[2];
    const int*   gl  = (const int*)  d_in[3];
    const float* gb  = (const float*)d_in[4];
    const float* pm  = (const float*)d_in[5];
    const int*   bgp = (const int*)  d_in[6];

    float* out      = (float*)d_out;
    float* out_lab  = out;
    float* out_box  = out + (size_t)NB * NA;
    float* out_sc   = out + (size_t)NB * NA * 5;

    // Side stream + events, created once on the (un-captured) correctness call
    static cudaStream_t s2 = nullptr;
    static cudaEvent_t ev_fork = nullptr, ev_join = nullptr;
    if (!s2) {
        cudaStreamCreateWithFlags(&s2, cudaStreamNonBlocking);
        cudaEventCreateWithFlags(&ev_fork, cudaEventDisableTiming);
        cudaEventCreateWithFlags(&ev_join, cudaEventDisableTiming);
    }

    // Fork: big memset of the scores region runs concurrently with topk/assign
    cudaEventRecord(ev_fork, 0);
    cudaStreamWaitEvent(s2, ev_fork, 0);
    cudaMemsetAsync(out_sc, 0, (size_t)NB * NA * NC * sizeof(float), s2);
    cudaEventRecord(ev_join, s2);

    k_init<<<(NB * NA + 255) / 256, 256>>>();
    k_topk<<<NB * NM, 256>>>(ps, pb, ap, gl, gb, pm);
    dim3 ga((NA + 255) / 256, NB);
    k_assign<<<ga, 256>>>(ps, pb, gl, gb, bgp, out_lab, out_box);

    // Join: scatter must land after the memset
    cudaStreamWaitEvent(0, ev_join, 0);
    k_scores<<<(NB * NA + 255) / 256, 256>>>(ps, pb, gl, gb, bgp, out_sc);
}

// round 3
// speedup vs baseline: 1.9022x; 1.1155x over previous
#include <cuda_runtime.h>

#define NB 32
#define NA 8400
#define NC 80
#define NM 64
#define KTOP 13
#define FEPS 1e-9f
#define CAP 2048
#define NBIN 32
#define MAXPOS (NB * NM * KTOP)

// Persistent scratch (device globals; no allocation allowed)
__device__ unsigned long long g_bits[NB * NA];   // topk∩ingts bits per anchor
__device__ float              g_maxmet[NB * NM];
__device__ float              g_maxiou[NB * NM];
__device__ float2             g_apb[NA];         // anchor points, y-bin order
__device__ int                g_aidx[NA];        // original anchor idx, y-bin order
__device__ int                g_binstart[NBIN + 1];
__device__ int                g_poscnt;
__device__ int2               g_poslist[MAXPOS]; // (global anchor idx, m)

__device__ __forceinline__ float iou_fn(float gx1, float gy1, float gx2, float gy2,
                                        float garea, float4 p) {
    float ix1 = fmaxf(gx1, p.x), iy1 = fmaxf(gy1, p.y);
    float ix2 = fminf(gx2, p.z), iy2 = fminf(gy2, p.w);
    float ov  = fmaxf(ix2 - ix1, 0.f) * fmaxf(iy2 - iy1, 0.f);
    float pa  = fmaxf(p.z - p.x, 0.f) * fmaxf(p.w - p.y, 0.f);
    return ov / (garea + pa - ov + FEPS);
}

__device__ __forceinline__ int ybin(float y) {
    int b = (int)(y * (NBIN / 640.0f));
    return min(max(b, 0), NBIN - 1);
}

// ---------------------------------------------------------------------------
__global__ void k_init() {
    int i = blockIdx.x * blockDim.x + threadIdx.x;
    if (i < NB * NA) g_bits[i] = 0ull;
    if (i < NB * NM) { g_maxmet[i] = 0.f; g_maxiou[i] = 0.f; }
    if (i == 0) g_poscnt = 0;
}

// ---------------------------------------------------------------------------
// Kernel: counting-sort anchors into NBIN y-bins (single block)
// ---------------------------------------------------------------------------
__global__ __launch_bounds__(1024)
void k_bin(const float* __restrict__ ap) {
    __shared__ int hist[NBIN];
    __shared__ int off[NBIN];
    int t = threadIdx.x;
    if (t < NBIN) hist[t] = 0;
    __syncthreads();
    const float2* apv = (const float2*)ap;
    for (int a = t; a < NA; a += 1024) atomicAdd(&hist[ybin(apv[a].y)], 1);
    __syncthreads();
    if (t == 0) {
        int acc = 0;
        for (int i = 0; i < NBIN; i++) { off[i] = acc; g_binstart[i] = acc; acc += hist[i]; }
        g_binstart[NBIN] = acc;
    }
    __syncthreads();
    for (int a = t; a < NA; a += 1024) {
        float2 c = apv[a];
        int pos = atomicAdd(&off[ybin(c.y)], 1);
        g_apb[pos]  = c;
        g_aidx[pos] = a;
    }
}

// ---------------------------------------------------------------------------
// Kernel: per (b,m) — scan only y-bins overlapping the gt box, compact
// candidates as unique packed keys, select top-13, scatter bits.
// ---------------------------------------------------------------------------
__global__ __launch_bounds__(256)
void k_topk(const float* __restrict__ ps,
            const float* __restrict__ pb,
            const int*   __restrict__ gl,
            const float* __restrict__ gb,
            const float* __restrict__ pm)
{
    int bm = blockIdx.x;
    if (pm[bm] == 0.f) return;
    int b = bm >> 6, m = bm & 63;

    __shared__ unsigned long long keys[CAP];
    __shared__ unsigned long long wred[8];
    __shared__ unsigned long long s_kprev;
    __shared__ int s_cnt;

    int t = threadIdx.x, lane = t & 31;
    if (t == 0) s_cnt = 0;
    __syncthreads();

    float gx1 = gb[bm * 4 + 0], gy1 = gb[bm * 4 + 1];
    float gx2 = gb[bm * 4 + 2], gy2 = gb[bm * 4 + 3];
    float garea = fmaxf(gx2 - gx1, 0.f) * fmaxf(gy2 - gy1, 0.f);
    int lab = gl[bm];

    const float4* pbv = (const float4*)pb + (size_t)b * NA;
    const float*  psb = ps + (size_t)b * NA * NC + lab;

    int lo = g_binstart[ybin(gy1)];
    int hi = g_binstart[ybin(gy2) + 1];

    // Phase 1: candidate compaction over the y-bin window
    for (int base = lo; base < hi; base += 256) {
        int i = base + t;
        bool inb = i < hi;
        float d = -1.f;
        int a = 0;
        if (inb) {
            float2 c = g_apb[i];
            a = g_aidx[i];
            d = fminf(fminf(c.x - gx1, c.y - gy1), fminf(gx2 - c.x, gy2 - c.y));
        }
        bool pred = inb && (d > FEPS);
        unsigned act = __ballot_sync(0xffffffffu, pred);
        if (pred) {
            float4 p   = pbv[a];
            float  iou = iou_fn(gx1, gy1, gx2, gy2, garea, p);
            float  cls = __ldg(psb + (size_t)a * NC);
            float  i2  = iou * iou;
            float  met = cls * (i2 * i2 * i2);
            unsigned long long key =
                ((unsigned long long)__float_as_uint(met) << 32) | (unsigned)(NA - a);
            int rank   = __popc(act & ((1u << lane) - 1u));
            int leader = __ffs(act) - 1;
            int pos;
            if (lane == leader) pos = atomicAdd(&s_cnt, __popc(act));
            pos = __shfl_sync(act, pos, leader) + rank;
            if (pos < CAP) keys[pos] = key;
        }
    }
    __syncthreads();
    int n = min(s_cnt, CAP);

    // Phase 2: 13 passes of "max key strictly below previous winner"
    unsigned long long kprev = 0xFFFFFFFFFFFFFFFFull;
    for (int k = 0; k < KTOP; k++) {
        unsigned long long best = 0ull;
        for (int i = t; i < n; i += 256) {
            unsigned long long kk = keys[i];
            if (kk < kprev && kk > best) best = kk;
        }
        #pragma unroll
        for (int s = 16; s; s >>= 1) {
            unsigned long long o = __shfl_down_sync(0xffffffffu, best, s);
            if (o > best) best = o;
        }
        if (lane == 0) wred[t >> 5] = best;
        __syncthreads();
        if (t < 32) {
            unsigned long long b2 = (t < 8) ? wred[t] : 0ull;
            #pragma unroll
            for (int s = 4; s; s >>= 1) {
                unsigned long long o = __shfl_down_sync(0xffffffffu, b2, s);
                if (o > b2) b2 = o;
            }
            if (t == 0) {
                s_kprev = b2;
                if (b2) {
                    int aidx = NA - (int)(b2 & 0xffffffffu);
                    atomicOr(&g_bits[(size_t)b * NA + aidx], 1ull << m);
                }
            }
        }
        __syncthreads();
        kprev = s_kprev;
        if (!kprev) break;
    }
}

// ---------------------------------------------------------------------------
// Kernel: per anchor — resolve multi-assignment, emit labels/bboxes, maxima,
// append positives to compact list.
// ---------------------------------------------------------------------------
__global__ __launch_bounds__(256)
void k_assign(const float* __restrict__ ps,
              const float* __restrict__ pb,
              const int*   __restrict__ gl,
              const float* __restrict__ gb,
              const int*   __restrict__ bgp,
              float* __restrict__ out_lab,   // [B,A]
              float* __restrict__ out_box)   // [B,A,4]
{
    int b = blockIdx.y;
    int t = threadIdx.x;
    __shared__ float sgb[NM * 4];
    __shared__ int   sgl[NM];
    if (t < NM * 4) sgb[t] = gb[b * NM * 4 + t];
    if (t < NM)     sgl[t] = gl[b * NM + t];
    __syncthreads();

    int a = blockIdx.x * 256 + t;
    size_t ia = (size_t)b * NA + a;
    unsigned long long bits = (a < NA) ? g_bits[ia] : 0ull;

    int mfin = -1;
    if (bits) {
        if (__popcll(bits) > 1) {
            float4 p = ((const float4*)pb)[ia];
            float bestv = -1.f; int bestm = 0;
            for (int m = 0; m < NM; m++) {
                float gx1 = sgb[4*m], gy1 = sgb[4*m+1], gx2 = sgb[4*m+2], gy2 = sgb[4*m+3];
                float ga = fmaxf(gx2 - gx1, 0.f) * fmaxf(gy2 - gy1, 0.f);
                float iou = iou_fn(gx1, gy1, gx2, gy2, ga, p);
                if (iou > bestv) { bestv = iou; bestm = m; }
            }
            mfin = bestm;
        } else {
            mfin = __ffsll((long long)bits) - 1;
        }
    }

    bool pos = (mfin >= 0);
    // warp-aggregated append of positives
    unsigned act = __ballot_sync(0xffffffffu, pos);
    if (pos) {
        int rank = __popc(act & ((1u << (t & 31)) - 1u));
        int leader = __ffs(act) - 1;
        int base;
        if ((t & 31) == leader) base = atomicAdd(&g_poscnt, __popc(act));
        base = __shfl_sync(act, base, leader) + rank;
        g_poslist[base] = make_int2((int)ia, mfin);
    }
    if (a >= NA) return;

    int first = pos ? mfin : 0;
    out_lab[ia] = (float)(pos ? sgl[first] : *bgp);
    float4 ob = {sgb[4*first], sgb[4*first+1], sgb[4*first+2], sgb[4*first+3]};
    ((float4*)out_box)[ia] = ob;

    if (pos) {
        float4 p = ((const float4*)pb)[ia];
        int m = mfin;
        float gx1 = sgb[4*m], gy1 = sgb[4*m+1], gx2 = sgb[4*m+2], gy2 = sgb[4*m+3];
        float ga = fmaxf(gx2 - gx1, 0.f) * fmaxf(gy2 - gy1, 0.f);
        float iou = iou_fn(gx1, gy1, gx2, gy2, ga, p);
        float cls = __ldg(&ps[ia * NC + sgl[m]]);
        float i2 = iou * iou;
        float align = cls * (i2 * i2 * i2);
        atomicMax((int*)&g_maxmet[b * NM + m], __float_as_int(align));
        atomicMax((int*)&g_maxiou[b * NM + m], __float_as_int(iou));
    }
}

// ---------------------------------------------------------------------------
// Kernel: over the compact positive list — normalized score scatter
// ---------------------------------------------------------------------------
__global__ __launch_bounds__(256)
void k_scores(const float* __restrict__ ps,
              const float* __restrict__ pb,
              const int*   __restrict__ gl,
              const float* __restrict__ gb,
              const int*   __restrict__ bgp,
              float* __restrict__ out_sc)    // [B,A,C]
{
    int tid = blockIdx.x * 256 + threadIdx.x;
    if (tid >= g_poscnt) return;
    int2 e = g_poslist[tid];
    size_t ia = (size_t)(unsigned)e.x;
    int m = e.y;
    int b = (int)(ia / NA);
    int bmi = b * NM + m;

    float4 p = ((const float4*)pb)[ia];
    float gx1 = gb[bmi*4], gy1 = gb[bmi*4+1], gx2 = gb[bmi*4+2], gy2 = gb[bmi*4+3];
    float ga = fmaxf(gx2 - gx1, 0.f) * fmaxf(gy2 - gy1, 0.f);
    float iou = iou_fn(gx1, gy1, gx2, gy2, ga, p);
    int lab = gl[bmi];
    float cls = __ldg(&ps[ia * NC + lab]);
    float i2 = iou * iou;
    float align = cls * (i2 * i2 * i2);
    float factor = align / (g_maxmet[bmi] + FEPS) * g_maxiou[bmi];

    int bg = *bgp;
    int col = (lab < bg) ? lab : (lab - 1);
    out_sc[ia * NC + col] = factor;
}

// ---------------------------------------------------------------------------
extern "C" void kernel_launch(void* const* d_in, const int* in_sizes, int n_in,
                              void* d_out, int out_size) {
    const float* ps  = (const float*)d_in[0];
    const float* pb  = (const float*)d_in[1];
    const float* ap  = (const float*)d_in[2];
    const int*   gl  = (const int*)  d_in[3];
    const float* gb  = (const float*)d_in[4];
    const float* pm  = (const float*)d_in[5];
    const int*   bgp = (const int*)  d_in[6];

    float* out      = (float*)d_out;
    float* out_lab  = out;
    float* out_box  = out + (size_t)NB * NA;
    float* out_sc   = out + (size_t)NB * NA * 5;

    static cudaStream_t s2 = nullptr;
    static cudaEvent_t ev_fork = nullptr, ev_join = nullptr;
    if (!s2) {
        cudaStreamCreateWithFlags(&s2, cudaStreamNonBlocking);
        cudaEventCreateWithFlags(&ev_fork, cudaEventDisableTiming);
        cudaEventCreateWithFlags(&ev_join, cudaEventDisableTiming);
    }

    // Fork: 86 MB memset overlaps bin/init/topk
    cudaEventRecord(ev_fork, 0);
    cudaStreamWaitEvent(s2, ev_fork, 0);
    cudaMemsetAsync(out_sc, 0, (size_t)NB * NA * NC * sizeof(float), s2);
    cudaEventRecord(ev_join, s2);

    k_bin<<<1, 1024>>>(ap);
    k_init<<<(NB * NA + 255) / 256, 256>>>();
    k_topk<<<NB * NM, 256>>>(ps, pb, gl, gb, pm);
    dim3 ga((NA + 255) / 256, NB);
    k_assign<<<ga, 256>>>(ps, pb, gl, gb, bgp, out_lab, out_box);

    cudaStreamWaitEvent(0, ev_join, 0);
    k_scores<<<(MAXPOS + 255) / 256, 256>>>(ps, pb, gl, gb, bgp, out_sc);
}